// round 2
// baseline (speedup 1.0000x reference)
#include <cuda_runtime.h>
#include <math.h>

#define BB 4
#define CC 64
#define NN 4096
#define RR 4
#define EPSF 1e-6f
#define PSS 68   // padded row stride for P tile (floats)

// -------- scratch (device globals; no allocation allowed) --------
__device__ float g_stat[BB][CC][6];        // s1,q1,s2,q2,sx,qx per (b,c)
__device__ float g_se[BB][CC];             // SE sigmoid gate
__device__ float g_W[5][BB][CC][CC];       // folded weights, [ci][co]
__device__ float g_bias[5][BB][CC];        // folded bias
__device__ float g_proj[5][BB][CC][NN];    // q1,k1,q2,k2,v  [c][n]
__device__ float g_h[2][BB][CC][NN];       // attention outputs per branch

// ================= kernel 1: per-(b,c) sums over HW =================
__global__ void k_stats(const float* __restrict__ x1, const float* __restrict__ x2) {
    int bc = blockIdx.x;                       // b*CC + c
    const float* p1 = x1 + (size_t)bc * NN;
    const float* p2 = x2 + (size_t)bc * NN;
    float s1=0.f,q1=0.f,s2=0.f,q2=0.f,sx=0.f,qx=0.f;
    for (int i = threadIdx.x; i < NN; i += 256) {
        float a = p1[i], b_ = p2[i], s = a + b_;
        s1 += a; q1 += a*a; s2 += b_; q2 += b_*b_; sx += s; qx += s*s;
    }
    __shared__ float red[6][256];
    red[0][threadIdx.x]=s1; red[1][threadIdx.x]=q1; red[2][threadIdx.x]=s2;
    red[3][threadIdx.x]=q2; red[4][threadIdx.x]=sx; red[5][threadIdx.x]=qx;
    __syncthreads();
    for (int off=128; off>=1; off>>=1) {
        if (threadIdx.x < (unsigned)off) {
            #pragma unroll
            for (int k=0;k<6;k++) red[k][threadIdx.x] += red[k][threadIdx.x+off];
        }
        __syncthreads();
    }
    if (threadIdx.x < 6) g_stat[bc/CC][bc%CC][threadIdx.x] = red[threadIdx.x][0];
}

// ============ kernel 2: SE MLP + GroupNorm fold into weights ============
__global__ void k_prep(const float* __restrict__ se_w1, const float* __restrict__ se_w2,
                       const float* __restrict__ gamma, const float* __restrict__ beta,
                       const float* __restrict__ wq, const float* __restrict__ bq,
                       const float* __restrict__ wk, const float* __restrict__ bk,
                       const float* __restrict__ wv, const float* __restrict__ bv) {
    int b = blockIdx.x;
    int c = threadIdx.x;   // 0..63
    __shared__ float sy[CC], sh[RR], sA[3][CC], sBc[3][CC];
    float st[6], stp[6];
    #pragma unroll
    for (int k=0;k<6;k++) st[k] = g_stat[b][c][k];
    int cp = c ^ 1;  // group partner channel (groups of 2)
    #pragma unroll
    for (int k=0;k<6;k++) stp[k] = g_stat[b][cp][k];

    sy[c] = st[4] * (1.0f/NN);                 // SE mean of x = x1+x2
    __syncthreads();
    if (c < RR) {
        float h = 0.f;
        for (int ci=0; ci<CC; ci++) h += se_w1[c*CC+ci]*sy[ci];
        sh[c] = fmaxf(h, 0.f);
    }
    __syncthreads();
    {
        float z = 0.f;
        #pragma unroll
        for (int r=0;r<RR;r++) z += se_w2[c*RR+r]*sh[r];
        g_se[b][c] = 1.f/(1.f+__expf(-z));
    }
    const float inv = 1.0f/(2.0f*NN);
    float ga = gamma[c], be = beta[c];
    #pragma unroll
    for (int t=0;t<3;t++) {                     // t=0:x1, 1:x2, 2:x
        float mean = (st[2*t]+stp[2*t])*inv;
        float var  = (st[2*t+1]+stp[2*t+1])*inv - mean*mean;
        float rs = rsqrtf(var + EPSF);
        float A = rs*ga;
        sA[t][c] = A;
        sBc[t][c] = be - mean*A;
    }
    __syncthreads();
    // fold GN affine into each projection's weights (per batch)
    for (int p=0;p<5;p++) {
        const float* w  = (p==0||p==2)? wq : (p==1||p==3)? wk : wv;
        const float* bb = (p==0||p==2)? bq : (p==1||p==3)? bk : bv;
        int t = (p<2)?0 : (p<4)?1 : 2;
        float acc = bb[c];
        for (int ci=0; ci<CC; ci++) {
            float wvl = w[c*CC+ci];
            acc += wvl * sBc[t][ci];
            g_W[p][b][ci][c] = wvl * sA[t][ci];   // transposed for proj kernel
        }
        g_bias[p][b][c] = acc;
    }
}

// ================= kernel 3: the five 1x1-conv projections =================
__global__ void __launch_bounds__(256) k_proj(const float* __restrict__ x1,
                                              const float* __restrict__ x2) {
    int nt = blockIdx.x, p = blockIdx.y, b = blockIdx.z;
    int n0 = nt * 64;
    __shared__ float xs[CC][64];
    __shared__ float Wt[CC][CC];
    __shared__ float bias[CC];
    int tid = threadIdx.x;
    const float* s1 = x1 + (size_t)b*CC*NN + n0;
    const float* s2 = x2 + (size_t)b*CC*NN + n0;
    for (int idx = tid; idx < CC*64; idx += 256) {
        int ci = idx >> 6, n = idx & 63;
        float v;
        if (p < 2)       v = s1[(size_t)ci*NN + n];
        else if (p < 4)  v = s2[(size_t)ci*NN + n];
        else             v = s1[(size_t)ci*NN + n] + s2[(size_t)ci*NN + n];
        xs[ci][n] = v;
    }
    for (int idx = tid; idx < CC*CC; idx += 256)
        (&Wt[0][0])[idx] = (&g_W[p][b][0][0])[idx];
    if (tid < CC) bias[tid] = g_bias[p][b][tid];
    __syncthreads();

    int cg = tid >> 4;     // co block: 4*cg..
    int ng = tid & 15;     // n  block: 4*ng..
    float acc[4][4];
    #pragma unroll
    for (int i=0;i<4;i++){ float bv_ = bias[4*cg+i];
        #pragma unroll
        for (int j=0;j<4;j++) acc[i][j]=bv_; }
    for (int ci=0; ci<CC; ci++) {
        float4 w4 = *(const float4*)&Wt[ci][4*cg];
        float4 x4 = *(const float4*)&xs[ci][4*ng];
        float wa[4]={w4.x,w4.y,w4.z,w4.w};
        float xa[4]={x4.x,x4.y,x4.z,x4.w};
        #pragma unroll
        for (int i=0;i<4;i++)
            #pragma unroll
            for (int j=0;j<4;j++) acc[i][j] += wa[i]*xa[j];
    }
    float* out = &g_proj[p][b][0][0] + n0;
    #pragma unroll
    for (int i=0;i<4;i++) {
        float4 v = make_float4(acc[i][0],acc[i][1],acc[i][2],acc[i][3]);
        *(float4*)&out[(size_t)(4*cg+i)*NN + 4*ng] = v;
    }
}

// ================= kernel 4: flash attention (64q tile) =================
__global__ void __launch_bounds__(256) k_attn() {
    extern __shared__ float sm[];
    float* Qs = sm;                 // [c][i]  4096
    float* Ks = Qs + 4096;          // [c][j]  4096
    float* Vs = Ks + 4096;          // [c][j] XOR-swizzled 4096
    float* Ps = Vs + 4096;          // [i][j] padded stride PSS
    __shared__ float rm[64], rl[64], rcorr[64];

    int qt = blockIdx.x;
    int bbi = blockIdx.y;
    int b = bbi >> 1, br = bbi & 1;
    const float* Q  = &g_proj[br?2:0][b][0][0];
    const float* Kp = &g_proj[br?3:1][b][0][0];
    const float* Vp = &g_proj[4][b][0][0];
    int tid = threadIdx.x;

    if (tid < 64) { rm[tid] = -INFINITY; rl[tid] = 0.f; rcorr[tid] = 0.f; }
    for (int idx = tid; idx < 4096; idx += 256) {
        int c = idx >> 6, i = idx & 63;
        Qs[idx] = Q[(size_t)c*NN + qt*64 + i];
    }
    float O[4][4];
    #pragma unroll
    for (int i=0;i<4;i++)
        #pragma unroll
        for (int j=0;j<4;j++) O[i][j]=0.f;

    int rq = tid >> 4, cq = tid & 15;   // S-compute & O mapping
    int rr = tid >> 2, seg = tid & 3;   // softmax mapping

    for (int kt = 0; kt < 64; kt++) {
        __syncthreads();                 // protect Ks/Vs from prior PV reads
        int j0 = kt*64;
        for (int idx = tid; idx < 4096; idx += 256) {
            int c = idx >> 6, j = idx & 63;
            Ks[idx] = Kp[(size_t)c*NN + j0 + j];
            float vv = Vp[(size_t)c*NN + j0 + j];
            Vs[c*64 + (((j>>2) ^ (c&15))<<2) + (j&3)] = vv;
        }
        __syncthreads();
        // ---- S = scale * Q^T K ----
        {
            float s[4][4];
            #pragma unroll
            for (int i=0;i<4;i++)
                #pragma unroll
                for (int j=0;j<4;j++) s[i][j]=0.f;
            for (int c_=0;c_<64;c_++) {
                float4 qv = *(const float4*)&Qs[c_*64 + 4*rq];
                float4 kv = *(const float4*)&Ks[c_*64 + 4*cq];
                float qa[4]={qv.x,qv.y,qv.z,qv.w};
                float ka[4]={kv.x,kv.y,kv.z,kv.w};
                #pragma unroll
                for (int i=0;i<4;i++)
                    #pragma unroll
                    for (int j=0;j<4;j++) s[i][j] += qa[i]*ka[j];
            }
            #pragma unroll
            for (int i=0;i<4;i++) {
                float4 v = make_float4(s[i][0]*0.125f, s[i][1]*0.125f,
                                       s[i][2]*0.125f, s[i][3]*0.125f);
                *(float4*)&Ps[(4*rq+i)*PSS + 4*cq] = v;
            }
        }
        __syncthreads();
        // ---- online softmax, 4 threads per row ----
        {
            float vloc[16];
            float4* prow = (float4*)&Ps[rr*PSS + seg*16];
            #pragma unroll
            for (int u=0;u<4;u++) {
                float4 v = prow[u];
                vloc[4*u]=v.x; vloc[4*u+1]=v.y; vloc[4*u+2]=v.z; vloc[4*u+3]=v.w;
            }
            float mx = -INFINITY;
            #pragma unroll
            for (int u=0;u<16;u++) mx = fmaxf(mx, vloc[u]);
            mx = fmaxf(mx, __shfl_xor_sync(0xffffffffu, mx, 1));
            mx = fmaxf(mx, __shfl_xor_sync(0xffffffffu, mx, 2));
            float m_old = rm[rr];
            float m_new = fmaxf(m_old, mx);
            float ls = 0.f;
            #pragma unroll
            for (int u=0;u<16;u++) { float p_ = __expf(vloc[u]-m_new); vloc[u]=p_; ls += p_; }
            ls += __shfl_xor_sync(0xffffffffu, ls, 1);
            ls += __shfl_xor_sync(0xffffffffu, ls, 2);
            #pragma unroll
            for (int u=0;u<4;u++)
                prow[u] = make_float4(vloc[4*u],vloc[4*u+1],vloc[4*u+2],vloc[4*u+3]);
            if (seg == 0) {
                float corr = __expf(m_old - m_new);
                rm[rr] = m_new;
                rl[rr] = rl[rr]*corr + ls;
                rcorr[rr] = corr;
            }
        }
        __syncthreads();
        // ---- O = O*corr + P @ V^T ----
        {
            #pragma unroll
            for (int i=0;i<4;i++) {
                float cr = rcorr[4*rq+i];
                #pragma unroll
                for (int j=0;j<4;j++) O[i][j]*=cr;
            }
            for (int j4=0;j4<16;j4++) {
                float4 pv[4];
                #pragma unroll
                for (int i=0;i<4;i++) pv[i] = *(const float4*)&Ps[(4*rq+i)*PSS + 4*j4];
                float4 vv[4];
                #pragma unroll
                for (int m=0;m<4;m++) {
                    int c_ = cq + 16*m;
                    vv[m] = *(const float4*)&Vs[c_*64 + 4*(j4 ^ cq)];
                }
                #pragma unroll
                for (int i=0;i<4;i++) {
                    #pragma unroll
                    for (int m=0;m<4;m++) {
                        O[i][m] += pv[i].x*vv[m].x + pv[i].y*vv[m].y
                                 + pv[i].z*vv[m].z + pv[i].w*vv[m].w;
                    }
                }
            }
        }
    }
    // ---- finalize: divide by row sums, write h ----
    float* H = &g_h[br][b][0][0];
    #pragma unroll
    for (int i=0;i<4;i++) {
        float invl = 1.0f / rl[4*rq+i];
        #pragma unroll
        for (int m=0;m<4;m++) {
            int c_ = cq + 16*m;
            H[(size_t)c_*NN + qt*64 + 4*rq + i] = O[i][m]*invl;
        }
    }
}

// ================= kernel 5: final combine =================
__global__ void k_final(const float* __restrict__ x1, const float* __restrict__ x2,
                        float* __restrict__ out) {
    int idx4 = blockIdx.x*256 + threadIdx.x;    // over BB*CC*NN/4
    if (idx4 >= BB*CC*NN/4) return;
    int idx = idx4 * 4;
    int bc = idx >> 12;
    int b = bc >> 6, c = bc & 63;
    float se = g_se[b][c];
    float4 a1 = *(const float4*)&x1[idx];
    float4 a2 = *(const float4*)&x2[idx];
    float4 h1 = *(const float4*)(&g_h[0][0][0][0] + idx);
    float4 h2 = *(const float4*)(&g_h[1][0][0][0] + idx);
    float xs[4] = {a1.x+a2.x, a1.y+a2.y, a1.z+a2.z, a1.w+a2.w};
    float h1a[4]={h1.x,h1.y,h1.z,h1.w};
    float h2a[4]={h2.x,h2.y,h2.z,h2.w};
    float oa[4];
    #pragma unroll
    for (int k=0;k<4;k++) {
        float w = 1.f/(1.f+__expf(-xs[k]*se));
        oa[k] = 2.f*h1a[k]*w + 2.f*h2a[k]*(1.f-w);
    }
    *(float4*)&out[idx] = make_float4(oa[0],oa[1],oa[2],oa[3]);
}

// ================= launcher =================
extern "C" void kernel_launch(void* const* d_in, const int* in_sizes, int n_in,
                              void* d_out, int out_size) {
    const float* x1    = (const float*)d_in[0];
    const float* x2    = (const float*)d_in[1];
    const float* se_w1 = (const float*)d_in[2];
    const float* se_w2 = (const float*)d_in[3];
    const float* gam   = (const float*)d_in[4];
    const float* bet   = (const float*)d_in[5];
    const float* wq    = (const float*)d_in[6];
    const float* bq    = (const float*)d_in[7];
    const float* wk    = (const float*)d_in[8];
    const float* bk    = (const float*)d_in[9];
    const float* wv    = (const float*)d_in[10];
    const float* bv    = (const float*)d_in[11];
    float* out = (float*)d_out;

    k_stats<<<BB*CC, 256>>>(x1, x2);
    k_prep<<<BB, CC>>>(se_w1, se_w2, gam, bet, wq, bq, wk, bk, wv, bv);
    k_proj<<<dim3(64, 5, BB), 256>>>(x1, x2);
    cudaFuncSetAttribute(k_attn, cudaFuncAttributeMaxDynamicSharedMemorySize, 66560);
    k_attn<<<dim3(64, 8), 256, 66560>>>();
    k_final<<<(BB*CC*NN/4 + 255)/256, 256>>>(x1, x2, out);
}

// round 3
// speedup vs baseline: 1.0968x; 1.0968x over previous
#include <cuda_runtime.h>
#include <math.h>

#define BB 4
#define CC 64
#define NN 4096
#define RR 4
#define EPSF 1e-6f
#define PSS 68   // padded row stride for P tile (floats)

typedef unsigned long long u64;

// -------- packed f32x2 helpers (Blackwell FFMA2 path, PTX-only) --------
__device__ __forceinline__ u64 pk2(float lo, float hi) {
    u64 r; asm("mov.b64 %0, {%1,%2};" : "=l"(r) : "f"(lo), "f"(hi)); return r;
}
__device__ __forceinline__ void upk2(u64 v, float& lo, float& hi) {
    asm("mov.b64 {%0,%1}, %2;" : "=f"(lo), "=f"(hi) : "l"(v));
}
__device__ __forceinline__ u64 ffma2(u64 a, u64 b, u64 c) {
    u64 d; asm("fma.rn.f32x2 %0, %1, %2, %3;" : "=l"(d) : "l"(a), "l"(b), "l"(c)); return d;
}
__device__ __forceinline__ u64 fmul2(u64 a, u64 b) {
    u64 d; asm("mul.rn.f32x2 %0, %1, %2;" : "=l"(d) : "l"(a), "l"(b)); return d;
}

// -------- scratch (device globals; no allocation allowed) --------
__device__ float g_stat[BB][CC][6];        // s1,q1,s2,q2,sx,qx per (b,c)
__device__ float g_se[BB][CC];             // SE sigmoid gate
__device__ float g_W[5][BB][CC][CC];       // folded weights, [ci][co]
__device__ float g_bias[5][BB][CC];        // folded bias
__device__ float g_proj[5][BB][CC][NN];    // q1,k1,q2,k2,v  [c][n]
__device__ float g_h[2][BB][CC][NN];       // attention outputs per branch

// ================= kernel 1: per-(b,c) sums over HW =================
__global__ void k_stats(const float* __restrict__ x1, const float* __restrict__ x2) {
    int bc = blockIdx.x;                       // b*CC + c
    const float* p1 = x1 + (size_t)bc * NN;
    const float* p2 = x2 + (size_t)bc * NN;
    float s1=0.f,q1=0.f,s2=0.f,q2=0.f,sx=0.f,qx=0.f;
    for (int i = threadIdx.x; i < NN; i += 256) {
        float a = p1[i], b_ = p2[i], s = a + b_;
        s1 += a; q1 += a*a; s2 += b_; q2 += b_*b_; sx += s; qx += s*s;
    }
    __shared__ float red[6][256];
    red[0][threadIdx.x]=s1; red[1][threadIdx.x]=q1; red[2][threadIdx.x]=s2;
    red[3][threadIdx.x]=q2; red[4][threadIdx.x]=sx; red[5][threadIdx.x]=qx;
    __syncthreads();
    for (int off=128; off>=1; off>>=1) {
        if (threadIdx.x < (unsigned)off) {
            #pragma unroll
            for (int k=0;k<6;k++) red[k][threadIdx.x] += red[k][threadIdx.x+off];
        }
        __syncthreads();
    }
    if (threadIdx.x < 6) g_stat[bc/CC][bc%CC][threadIdx.x] = red[threadIdx.x][0];
}

// ============ kernel 2: SE MLP + GroupNorm fold into weights ============
__global__ void k_prep(const float* __restrict__ se_w1, const float* __restrict__ se_w2,
                       const float* __restrict__ gamma, const float* __restrict__ beta,
                       const float* __restrict__ wq, const float* __restrict__ bq,
                       const float* __restrict__ wk, const float* __restrict__ bk,
                       const float* __restrict__ wv, const float* __restrict__ bv) {
    int b = blockIdx.x;
    int c = threadIdx.x;   // 0..63
    __shared__ float sy[CC], sh[RR], sA[3][CC], sBc[3][CC];
    float st[6], stp[6];
    #pragma unroll
    for (int k=0;k<6;k++) st[k] = g_stat[b][c][k];
    int cp = c ^ 1;  // group partner channel (groups of 2)
    #pragma unroll
    for (int k=0;k<6;k++) stp[k] = g_stat[b][cp][k];

    sy[c] = st[4] * (1.0f/NN);                 // SE mean of x = x1+x2
    __syncthreads();
    if (c < RR) {
        float h = 0.f;
        for (int ci=0; ci<CC; ci++) h += se_w1[c*CC+ci]*sy[ci];
        sh[c] = fmaxf(h, 0.f);
    }
    __syncthreads();
    {
        float z = 0.f;
        #pragma unroll
        for (int r=0;r<RR;r++) z += se_w2[c*RR+r]*sh[r];
        g_se[b][c] = 1.f/(1.f+__expf(-z));
    }
    const float inv = 1.0f/(2.0f*NN);
    float ga = gamma[c], be = beta[c];
    #pragma unroll
    for (int t=0;t<3;t++) {                     // t=0:x1, 1:x2, 2:x
        float mean = (st[2*t]+stp[2*t])*inv;
        float var  = (st[2*t+1]+stp[2*t+1])*inv - mean*mean;
        float rs = rsqrtf(var + EPSF);
        float A = rs*ga;
        sA[t][c] = A;
        sBc[t][c] = be - mean*A;
    }
    __syncthreads();
    // fold GN affine into each projection's weights (per batch)
    for (int p=0;p<5;p++) {
        const float* w  = (p==0||p==2)? wq : (p==1||p==3)? wk : wv;
        const float* bb = (p==0||p==2)? bq : (p==1||p==3)? bk : bv;
        int t = (p<2)?0 : (p<4)?1 : 2;
        float acc = bb[c];
        for (int ci=0; ci<CC; ci++) {
            float wvl = w[c*CC+ci];
            acc += wvl * sBc[t][ci];
            g_W[p][b][ci][c] = wvl * sA[t][ci];   // transposed for proj kernel
        }
        g_bias[p][b][c] = acc;
    }
}

// ================= kernel 3: the five 1x1-conv projections =================
__global__ void __launch_bounds__(256) k_proj(const float* __restrict__ x1,
                                              const float* __restrict__ x2) {
    int nt = blockIdx.x, p = blockIdx.y, b = blockIdx.z;
    int n0 = nt * 64;
    __shared__ float xs[CC][64];
    __shared__ float Wt[CC][CC];
    __shared__ float bias[CC];
    int tid = threadIdx.x;
    const float* s1 = x1 + (size_t)b*CC*NN + n0;
    const float* s2 = x2 + (size_t)b*CC*NN + n0;
    for (int idx = tid; idx < CC*64; idx += 256) {
        int ci = idx >> 6, n = idx & 63;
        float v;
        if (p < 2)       v = s1[(size_t)ci*NN + n];
        else if (p < 4)  v = s2[(size_t)ci*NN + n];
        else             v = s1[(size_t)ci*NN + n] + s2[(size_t)ci*NN + n];
        xs[ci][n] = v;
    }
    for (int idx = tid; idx < CC*CC; idx += 256)
        (&Wt[0][0])[idx] = (&g_W[p][b][0][0])[idx];
    if (tid < CC) bias[tid] = g_bias[p][b][tid];
    __syncthreads();

    int cg = tid >> 4;     // co block: 4*cg..
    int ng = tid & 15;     // n  block: 4*ng..
    float acc[4][4];
    #pragma unroll
    for (int i=0;i<4;i++){ float bv_ = bias[4*cg+i];
        #pragma unroll
        for (int j=0;j<4;j++) acc[i][j]=bv_; }
    for (int ci=0; ci<CC; ci++) {
        float4 w4 = *(const float4*)&Wt[ci][4*cg];
        float4 x4 = *(const float4*)&xs[ci][4*ng];
        float wa[4]={w4.x,w4.y,w4.z,w4.w};
        float xa[4]={x4.x,x4.y,x4.z,x4.w};
        #pragma unroll
        for (int i=0;i<4;i++)
            #pragma unroll
            for (int j=0;j<4;j++) acc[i][j] += wa[i]*xa[j];
    }
    float* out = &g_proj[p][b][0][0] + n0;
    #pragma unroll
    for (int i=0;i<4;i++) {
        float4 v = make_float4(acc[i][0],acc[i][1],acc[i][2],acc[i][3]);
        *(float4*)&out[(size_t)(4*cg+i)*NN + 4*ng] = v;
    }
}

// ============== kernel 4: flash attention (64q tile, f32x2 math) ==============
// 128 threads. Per kt-iter (64 keys):
//   S:  thread tile 4i x 8j (j-quads {jq, jq+8}), packed FFMA2
//   PV: thread tile 4i x 8c, packed FFMA2 over j-pairs; acc lanes = even/odd j
// K/V tiles quad-XOR swizzled for conflict-free LDS.
__global__ void __launch_bounds__(128, 3) k_attn() {
    extern __shared__ float sm[];
    float* Qs = sm;                 // [c][i]  4096 (pre-scaled by 0.125)
    float* Ks = Qs + 4096;          // [c][j]  quad-swizzled
    float* Vs = Ks + 4096;          // [c][j]  quad-swizzled
    float* Ps = Vs + 4096;          // [i][j]  stride PSS
    __shared__ float rm[64], rl[64], rcorr[64];

    int qt = blockIdx.x;
    int bbi = blockIdx.y;
    int b = bbi >> 1, br = bbi & 1;
    const float* Q  = &g_proj[br?2:0][b][0][0] + qt*64;
    const float* Kp = &g_proj[br?3:1][b][0][0];
    const float* Vp = &g_proj[4][b][0][0];
    int tid = threadIdx.x;

    if (tid < 64) { rm[tid] = -INFINITY; rl[tid] = 0.f; }

    // load Q tile (scaled): 1024 float4s over 128 threads
    for (int idx4 = tid; idx4 < 1024; idx4 += 128) {
        int c = idx4 >> 4, i4 = (idx4 & 15) << 2;
        float4 v = *(const float4*)&Q[(size_t)c*NN + i4];
        v.x *= 0.125f; v.y *= 0.125f; v.z *= 0.125f; v.w *= 0.125f;
        *(float4*)&Qs[c*64 + i4] = v;
    }

    int iq = tid >> 3;          // i block (0..15): i = 4*iq+di
    int jq = tid & 7;           // j quads {jq, jq+8}
    int cq = tid & 7;           // PV: c = cq + 8*m
    int rr = tid >> 1, seg = tid & 1;  // softmax: 2 threads/row

    u64 acc[4][8];              // O accumulators, f32x2 (even/odd j lanes)
    #pragma unroll
    for (int i=0;i<4;i++)
        #pragma unroll
        for (int m=0;m<8;m++) acc[i][m] = 0ull;

    for (int kt = 0; kt < 64; kt++) {
        __syncthreads();                 // Ks/Vs/Ps safe to overwrite
        int j0 = kt*64;
        // ---- load K,V tile, swizzled: quad q4 -> q4 ^ (c&15) ----
        for (int idx4 = tid; idx4 < 1024; idx4 += 128) {
            int c = idx4 >> 4, q4 = idx4 & 15;
            int j = q4 << 2;
            float4 kv = *(const float4*)&Kp[(size_t)c*NN + j0 + j];
            float4 vv = *(const float4*)&Vp[(size_t)c*NN + j0 + j];
            int sq = ((q4 ^ (c & 15)) << 2);
            *(float4*)&Ks[c*64 + sq] = kv;
            *(float4*)&Vs[c*64 + sq] = vv;
        }
        __syncthreads();
        // ---- S = (Q*0.125)^T K : s2[di][0..1] = quad jq, [2..3] = quad jq+8 ----
        {
            u64 s2[4][4];
            #pragma unroll
            for (int i=0;i<4;i++)
                #pragma unroll
                for (int u=0;u<4;u++) s2[i][u] = 0ull;
            #pragma unroll 4
            for (int c_=0; c_<64; c_++) {
                float4 qv = *(const float4*)&Qs[c_*64 + 4*iq];
                u64 qd0 = pk2(qv.x, qv.x);
                u64 qd1 = pk2(qv.y, qv.y);
                u64 qd2 = pk2(qv.z, qv.z);
                u64 qd3 = pk2(qv.w, qv.w);
                int s = c_ & 15;
                ulonglong2 ka = *(const ulonglong2*)&Ks[c_*64 + 4*(jq ^ s)];
                ulonglong2 kb = *(const ulonglong2*)&Ks[c_*64 + 4*((jq + 8) ^ s)];
                s2[0][0]=ffma2(qd0,ka.x,s2[0][0]); s2[0][1]=ffma2(qd0,ka.y,s2[0][1]);
                s2[0][2]=ffma2(qd0,kb.x,s2[0][2]); s2[0][3]=ffma2(qd0,kb.y,s2[0][3]);
                s2[1][0]=ffma2(qd1,ka.x,s2[1][0]); s2[1][1]=ffma2(qd1,ka.y,s2[1][1]);
                s2[1][2]=ffma2(qd1,kb.x,s2[1][2]); s2[1][3]=ffma2(qd1,kb.y,s2[1][3]);
                s2[2][0]=ffma2(qd2,ka.x,s2[2][0]); s2[2][1]=ffma2(qd2,ka.y,s2[2][1]);
                s2[2][2]=ffma2(qd2,kb.x,s2[2][2]); s2[2][3]=ffma2(qd2,kb.y,s2[2][3]);
                s2[3][0]=ffma2(qd3,ka.x,s2[3][0]); s2[3][1]=ffma2(qd3,ka.y,s2[3][1]);
                s2[3][2]=ffma2(qd3,kb.x,s2[3][2]); s2[3][3]=ffma2(qd3,kb.y,s2[3][3]);
            }
            #pragma unroll
            for (int di=0; di<4; di++) {
                ulonglong2 pa; pa.x = s2[di][0]; pa.y = s2[di][1];
                ulonglong2 pb; pb.x = s2[di][2]; pb.y = s2[di][3];
                *(ulonglong2*)&Ps[(4*iq+di)*PSS + 4*jq]      = pa;
                *(ulonglong2*)&Ps[(4*iq+di)*PSS + 4*jq + 32] = pb;
            }
        }
        __syncthreads();
        // ---- online softmax: 2 threads per row, 32 cols each ----
        {
            float vloc[32];
            float* prow = &Ps[rr*PSS + 32*seg];
            #pragma unroll
            for (int u=0;u<8;u++) {
                float4 v = *(const float4*)&prow[4*u];
                vloc[4*u]=v.x; vloc[4*u+1]=v.y; vloc[4*u+2]=v.z; vloc[4*u+3]=v.w;
            }
            float mx = vloc[0];
            #pragma unroll
            for (int u=1;u<32;u++) mx = fmaxf(mx, vloc[u]);
            mx = fmaxf(mx, __shfl_xor_sync(0xffffffffu, mx, 1));
            float m_old = rm[rr];
            float m_new = fmaxf(m_old, mx);
            float ls = 0.f;
            #pragma unroll
            for (int u=0;u<32;u++) { float p_ = __expf(vloc[u]-m_new); vloc[u]=p_; ls += p_; }
            ls += __shfl_xor_sync(0xffffffffu, ls, 1);
            #pragma unroll
            for (int u=0;u<8;u++)
                *(float4*)&prow[4*u] = make_float4(vloc[4*u],vloc[4*u+1],vloc[4*u+2],vloc[4*u+3]);
            if (seg == 0) {
                float corr = __expf(m_old - m_new);
                rm[rr] = m_new;
                rl[rr] = rl[rr]*corr + ls;
                rcorr[rr] = corr;
            }
        }
        __syncthreads();
        // ---- O = O*corr + P @ V^T (packed over j-pairs) ----
        {
            #pragma unroll
            for (int di=0; di<4; di++) {
                u64 crd = pk2(rcorr[4*iq+di], rcorr[4*iq+di]);
                #pragma unroll
                for (int m=0;m<8;m++) acc[di][m] = fmul2(acc[di][m], crd);
            }
            #pragma unroll 2
            for (int j4=0; j4<16; j4++) {
                ulonglong2 p2[4];
                #pragma unroll
                for (int di=0; di<4; di++)
                    p2[di] = *(const ulonglong2*)&Ps[(4*iq+di)*PSS + 4*j4];
                #pragma unroll
                for (int m=0;m<8;m++) {
                    int c_ = cq + 8*m;
                    ulonglong2 v2 = *(const ulonglong2*)&Vs[c_*64 + 4*(j4 ^ (c_ & 15))];
                    acc[0][m] = ffma2(p2[0].x, v2.x, acc[0][m]);
                    acc[0][m] = ffma2(p2[0].y, v2.y, acc[0][m]);
                    acc[1][m] = ffma2(p2[1].x, v2.x, acc[1][m]);
                    acc[1][m] = ffma2(p2[1].y, v2.y, acc[1][m]);
                    acc[2][m] = ffma2(p2[2].x, v2.x, acc[2][m]);
                    acc[2][m] = ffma2(p2[2].y, v2.y, acc[2][m]);
                    acc[3][m] = ffma2(p2[3].x, v2.x, acc[3][m]);
                    acc[3][m] = ffma2(p2[3].y, v2.y, acc[3][m]);
                }
            }
        }
    }
    // ---- finalize: horizontal add lanes, divide by row sums, write h ----
    float* H = &g_h[br][b][0][0] + qt*64;
    #pragma unroll
    for (int di=0; di<4; di++) {
        float invl = 1.0f / rl[4*iq+di];
        #pragma unroll
        for (int m=0;m<8;m++) {
            int c_ = cq + 8*m;
            float lo, hi; upk2(acc[di][m], lo, hi);
            H[(size_t)c_*NN + 4*iq + di] = (lo + hi) * invl;
        }
    }
}

// ================= kernel 5: final combine =================
__global__ void k_final(const float* __restrict__ x1, const float* __restrict__ x2,
                        float* __restrict__ out) {
    int idx4 = blockIdx.x*256 + threadIdx.x;    // over BB*CC*NN/4
    if (idx4 >= BB*CC*NN/4) return;
    int idx = idx4 * 4;
    int bc = idx >> 12;
    int b = bc >> 6, c = bc & 63;
    float se = g_se[b][c];
    float4 a1 = *(const float4*)&x1[idx];
    float4 a2 = *(const float4*)&x2[idx];
    float4 h1 = *(const float4*)(&g_h[0][0][0][0] + idx);
    float4 h2 = *(const float4*)(&g_h[1][0][0][0] + idx);
    float xs[4] = {a1.x+a2.x, a1.y+a2.y, a1.z+a2.z, a1.w+a2.w};
    float h1a[4]={h1.x,h1.y,h1.z,h1.w};
    float h2a[4]={h2.x,h2.y,h2.z,h2.w};
    float oa[4];
    #pragma unroll
    for (int k=0;k<4;k++) {
        float w = 1.f/(1.f+__expf(-xs[k]*se));
        oa[k] = 2.f*h1a[k]*w + 2.f*h2a[k]*(1.f-w);
    }
    *(float4*)&out[idx] = make_float4(oa[0],oa[1],oa[2],oa[3]);
}

// ================= launcher =================
extern "C" void kernel_launch(void* const* d_in, const int* in_sizes, int n_in,
                              void* d_out, int out_size) {
    const float* x1    = (const float*)d_in[0];
    const float* x2    = (const float*)d_in[1];
    const float* se_w1 = (const float*)d_in[2];
    const float* se_w2 = (const float*)d_in[3];
    const float* gam   = (const float*)d_in[4];
    const float* bet   = (const float*)d_in[5];
    const float* wq    = (const float*)d_in[6];
    const float* bq    = (const float*)d_in[7];
    const float* wk    = (const float*)d_in[8];
    const float* bk    = (const float*)d_in[9];
    const float* wv    = (const float*)d_in[10];
    const float* bv    = (const float*)d_in[11];
    float* out = (float*)d_out;

    k_stats<<<BB*CC, 256>>>(x1, x2);
    k_prep<<<BB, CC>>>(se_w1, se_w2, gam, bet, wq, bq, wk, bk, wv, bv);
    k_proj<<<dim3(64, 5, BB), 256>>>(x1, x2);
    cudaFuncSetAttribute(k_attn, cudaFuncAttributeMaxDynamicSharedMemorySize, 66560);
    k_attn<<<dim3(64, 8), 128, 66560>>>();
    k_final<<<(BB*CC*NN/4 + 255)/256, 256>>>(x1, x2, out);
}